// round 13
// baseline (speedup 1.0000x reference)
#include <cuda_runtime.h>
#include <cuda_fp16.h>
#include <cstdint>

// B=64,S=2048,D=64,E=64,H=512,F=4,V=32000
#define TOKENS (64 * 2048)
#define MT 32
#define NBLK (TOKENS / MT)  // 4096
typedef unsigned long long ULL;
typedef unsigned int U32;

__device__ float g_logdet[4];
// B tiles, f16x2, warp-slice-contiguous: [kt][w(8)][lane(32)][nt(8)][rr(2)]
__device__ U32 g_W0p[4 * 6 * 4096];   // K'=96 (6 kt)
__device__ U32 g_W1p[4 * 32 * 4096];  // K=512
// W2 cols 64..127: [tile(8)][w(8)][lane(32)][s(4)][rr(2)]
__device__ U32 g_W2p[4 * 8 * 2048];

// smem float offsets (total 27520 floats = 110080 B -> 2 CTAs/SM)
#define ZE 0       // 32 x 68 fp32 z
#define EXT 2176   // 32 x 64 fp32 ext (persistent)
#define SB 4224    // b0[512] b1[512] b2[128] ab[128]
#define G3A 5504   // 1536 u32: A frags [mtl(2)][kt(6)][128]
#define HA 7040    // 8192 u32: h A frags [mtl(2)][kt(32)][128]
#define RING 15232 // 48KB: per-warp rings (N512: w*6144B x3 slots; G5: w*3072B)
#define SMEMF 27520
#define SMEMB (SMEMF * 4)

// ---------------- helpers ----------------
__device__ __forceinline__ ULL dup2(float a) {
    ULL r; U32 ai = __float_as_uint(a);
    asm("mov.b64 %0, {%1, %1};" : "=l"(r) : "r"(ai));
    return r;
}
__device__ __forceinline__ void fma2(ULL& d, ULL a, ULL b) {
    asm("fma.rn.f32x2 %0, %1, %2, %0;" : "+l"(d) : "l"(a), "l"(b));
}
__device__ __forceinline__ float2 unpk(ULL v) {
    U32 lo, hi;
    asm("mov.b64 {%0, %1}, %2;" : "=r"(lo), "=r"(hi) : "l"(v));
    float2 r; r.x = __uint_as_float(lo); r.y = __uint_as_float(hi);
    return r;
}
__device__ __forceinline__ float gelu(float x) {
    return 0.5f * x * (1.0f + erff(x * 0.70710678118654752440f));
}
__device__ __forceinline__ U32 pack_h(float lo, float hi) {
    U32 r;
    asm("cvt.rn.f16x2.f32 %0, %1, %2;" : "=r"(r) : "f"(hi), "f"(lo));
    return r;
}
__device__ __forceinline__ float2 unpk_h(U32 v) {
    __half2 h = *reinterpret_cast<__half2*>(&v);
    return __half22float2(h);
}
__device__ __forceinline__ U32 smem_u32(const void* p) {
    U32 a;
    asm("{ .reg .u64 t; cvta.to.shared.u64 t, %1; cvt.u32.u64 %0, t; }" : "=r"(a) : "l"(p));
    return a;
}
#define CPA16(d, s) asm volatile("cp.async.cg.shared.global [%0], [%1], 16;" ::"r"(d), "l"(s))
#define CPC() asm volatile("cp.async.commit_group;" ::: "memory")
#define CPW0() asm volatile("cp.async.wait_group 0;" ::: "memory")
#define CPW1() asm volatile("cp.async.wait_group 1;" ::: "memory")

// f16 x f16 -> f16 accumulate (2 c-regs of f16x2)
__device__ __forceinline__ void mma16h(U32* c, uint4 a, uint2 b) {
    asm volatile(
        "mma.sync.aligned.m16n8k16.row.col.f16.f16.f16.f16 "
        "{%0,%1},{%2,%3,%4,%5},{%6,%7},{%0,%1};"
        : "+r"(c[0]), "+r"(c[1])
        : "r"(a.x), "r"(a.y), "r"(a.z), "r"(a.w), "r"(b.x), "r"(b.y));
}
__device__ __forceinline__ void stage_cp(U32 dstU, const float* src, int n4, int tid) {
    for (int i = tid; i < n4; i += 256) CPA16(dstU + i * 16, src + i * 4);
}

// ---------------- weight packs (warp-slice-contiguous f16 frags) -------------
__global__ void packB(const float* __restrict__ src, U32* __restrict__ dst, int N,
                      int KT, int kMode) {
    int f = blockIdx.y, kt = blockIdx.x, tid = threadIdx.x;
    const float* s = src + (long long)f * (kMode ? 128 : 512) * N;
    U32* d = dst + (long long)(f * KT + kt) * 4096;
    for (int i = tid; i < 4096; i += 256) {
        int w = i >> 9, lane = (i >> 4) & 31, nt = (i >> 1) & 7, rr = i & 1;
        int ntg = w * 8 + nt;
        int n = ntg * 8 + (lane >> 2);
        int k0 = kt * 16 + 2 * (lane & 3) + 8 * rr;
        if (kMode && k0 >= 32) k0 += 32;  // W0: skip masked-z rows 32..63
        d[i] = pack_h(s[k0 * N + n], s[(k0 + 1) * N + n]);
    }
}
// W2 cols 64..127
__global__ void packW2(const float* __restrict__ W2, U32* __restrict__ dst) {
    int f = blockIdx.y, t = blockIdx.x, tid = threadIdx.x;
    const float* s = W2 + (long long)f * 512 * 128;
    U32* d = dst + (f * 8 + t) * 2048;
    for (int i = tid; i < 2048; i += 256) {
        int w = i >> 8, j = i & 255;
        int lane = j >> 3, jj = j & 7;
        int ss = jj >> 1, rr = jj & 1;
        int n = 64 + w * 8 + (lane >> 2);
        int k0 = (t * 4 + ss) * 16 + 2 * (lane & 3) + 8 * rr;
        d[i] = pack_h(s[k0 * 128 + n], s[(k0 + 1) * 128 + n]);
    }
}

// ---------------- slogdet (64x64 LU) ----------------
__global__ void logdet_kernel(const float* __restrict__ cW) {
    __shared__ float A[64][65];
    __shared__ int piv;
    int f = blockIdx.x, tid = threadIdx.x;
    for (int j = 0; j < 64; j++) A[j][tid] = cW[f * 4096 + j * 64 + tid];
    __syncthreads();
    for (int j = 0; j < 64; j++) {
        if (tid == 0) {
            int p = j; float mv = fabsf(A[j][j]);
            for (int i = j + 1; i < 64; i++) {
                float v = fabsf(A[i][j]);
                if (v > mv) { mv = v; p = i; }
            }
            piv = p;
        }
        __syncthreads();
        int p = piv;
        if (p != j) { float t = A[j][tid]; A[j][tid] = A[p][tid]; A[p][tid] = t; }
        __syncthreads();
        if (tid > j) {
            float fct = A[tid][j] / A[j][j];
            for (int k = j; k < 64; k++) A[tid][k] -= fct * A[j][k];
        }
        __syncthreads();
    }
    if (tid == 0) {
        float s = 0.f;
        for (int j = 0; j < 64; j++) s += logf(fabsf(A[j][j]));
        g_logdet[f] = s;
    }
}
__global__ void init_ldj_kernel(float* __restrict__ ldj) {
    if (threadIdx.x < 64) {
        float s = g_logdet[0] + g_logdet[1] + g_logdet[2] + g_logdet[3];
        ldj[threadIdx.x] = 2048.0f * s;
    }
}

// ------- gemm: per-warp private 3x2KB ring, ZERO intra-gemm barriers ---------
template <int ITERS, int KTA>
__device__ __forceinline__ void gemmW(U32 (*acc)[2], const U32* __restrict__ Bg,
                                      const U32* __restrict__ AU, U32 ringU,
                                      const char* __restrict__ ringC, int lane,
                                      int wid) {
    __syncthreads();  // ring free, A frags ready
    const U32 wrU = ringU + wid * 6144;
    const char* wrC = ringC + wid * 6144;
    const U32 sw = (U32)((lane & 6) << 3);
    const U32 lo = (U32)lane * 64;
#pragma unroll
    for (int t = 0; t < 2 && t < ITERS; t++) {
        const U32* g = Bg + t * 4096 + wid * 512 + lane * 16;
#pragma unroll
        for (int q = 0; q < 4; q++)
            CPA16(wrU + t * 2048 + ((lo + q * 16) ^ sw), (const float*)(g + q * 4));
        CPC();
    }
#pragma unroll 1
    for (int it = 0; it < ITERS; it++) {
        if (it + 1 < ITERS) { CPW1(); } else { CPW0(); }
        if (it + 2 < ITERS) {
            int sl2 = (it + 2) % 3;
            const U32* g = Bg + (it + 2) * 4096 + wid * 512 + lane * 16;
#pragma unroll
            for (int q = 0; q < 4; q++)
                CPA16(wrU + sl2 * 2048 + ((lo + q * 16) ^ sw), (const float*)(g + q * 4));
            CPC();
        }
        const char* sb = wrC + (it % 3) * 2048;
        uint4 b0 = *(const uint4*)(sb + ((lo + 0) ^ sw));
        uint4 b1 = *(const uint4*)(sb + ((lo + 16) ^ sw));
        uint4 b2 = *(const uint4*)(sb + ((lo + 32) ^ sw));
        uint4 b3 = *(const uint4*)(sb + ((lo + 48) ^ sw));
        uint4 a0 = *(const uint4*)(AU + (0 * KTA + it) * 128 + lane * 4);
        uint4 a1 = *(const uint4*)(AU + (1 * KTA + it) * 128 + lane * 4);
        uint2 bv;
        bv = make_uint2(b0.x, b0.y); mma16h(acc[0], a0, bv); mma16h(acc[8], a1, bv);
        bv = make_uint2(b0.z, b0.w); mma16h(acc[1], a0, bv); mma16h(acc[9], a1, bv);
        bv = make_uint2(b1.x, b1.y); mma16h(acc[2], a0, bv); mma16h(acc[10], a1, bv);
        bv = make_uint2(b1.z, b1.w); mma16h(acc[3], a0, bv); mma16h(acc[11], a1, bv);
        bv = make_uint2(b2.x, b2.y); mma16h(acc[4], a0, bv); mma16h(acc[12], a1, bv);
        bv = make_uint2(b2.z, b2.w); mma16h(acc[5], a0, bv); mma16h(acc[13], a1, bv);
        bv = make_uint2(b3.x, b3.y); mma16h(acc[6], a0, bv); mma16h(acc[14], a1, bv);
        bv = make_uint2(b3.z, b3.w); mma16h(acc[7], a0, bv); mma16h(acc[15], a1, bv);
    }
}

// ------- G5 gemm: per-warp 3x1KB ring, 4 k-steps per 8KB tile, N=64 ----------
__device__ __forceinline__ void gemmG5(U32 (*acc)[2], const U32* __restrict__ Bg,
                                       const U32* __restrict__ AU, U32 ringU,
                                       const char* __restrict__ ringC, int lane,
                                       int wid) {
    __syncthreads();
    const U32 wrU = ringU + wid * 3072;
    const char* wrC = ringC + wid * 3072;
    const U32 sw = (U32)((lane & 4) << 2);
    const U32 lo = (U32)lane * 32;
#pragma unroll
    for (int t = 0; t < 2; t++) {
        const U32* g = Bg + t * 2048 + wid * 256 + lane * 8;
        CPA16(wrU + t * 1024 + ((lo + 0) ^ sw), (const float*)(g));
        CPA16(wrU + t * 1024 + ((lo + 16) ^ sw), (const float*)(g + 4));
        CPC();
    }
#pragma unroll 1
    for (int it = 0; it < 8; it++) {
        if (it + 1 < 8) { CPW1(); } else { CPW0(); }
        if (it + 2 < 8) {
            int sl2 = (it + 2) % 3;
            const U32* g = Bg + (it + 2) * 2048 + wid * 256 + lane * 8;
            CPA16(wrU + sl2 * 1024 + ((lo + 0) ^ sw), (const float*)(g));
            CPA16(wrU + sl2 * 1024 + ((lo + 16) ^ sw), (const float*)(g + 4));
            CPC();
        }
        const char* sb = wrC + (it % 3) * 1024;
        uint4 q0 = *(const uint4*)(sb + ((lo + 0) ^ sw));
        uint4 q1 = *(const uint4*)(sb + ((lo + 16) ^ sw));
#pragma unroll
        for (int s = 0; s < 4; s++) {
            int kt = it * 4 + s;
            uint2 bv = (s == 0) ? make_uint2(q0.x, q0.y)
                     : (s == 1) ? make_uint2(q0.z, q0.w)
                     : (s == 2) ? make_uint2(q1.x, q1.y)
                                : make_uint2(q1.z, q1.w);
            uint4 a0 = *(const uint4*)(AU + (0 * 32 + kt) * 128 + lane * 4);
            uint4 a1 = *(const uint4*)(AU + (1 * 32 + kt) * 128 + lane * 4);
            mma16h(acc[0], a0, bv);
            mma16h(acc[1], a1, bv);
        }
    }
}

// epilogue: gelu(acc+bias) -> hA f16 A-frags (mtl 0..1, nt 0..7 per warp)
__device__ __forceinline__ void epiH(U32 (*acc)[2], const float* __restrict__ bias,
                                     U32* __restrict__ hAU, int lane, int wid) {
    int c2 = 2 * (lane & 3);
#pragma unroll
    for (int mtl = 0; mtl < 2; mtl++)
#pragma unroll
        for (int nt = 0; nt < 8; nt++) {
            int ntg = wid * 8 + nt;
            float2 v0 = unpk_h(acc[mtl * 8 + nt][0]);
            float2 v1 = unpk_h(acc[mtl * 8 + nt][1]);
            int n0 = ntg * 8 + c2;
            float b0v = bias[n0], b1v = bias[n0 + 1];
            U32 base = (U32)(mtl * 32 + (ntg >> 1)) * 128 + lane * 4 + 2 * (ntg & 1);
            hAU[base + 0] = pack_h(gelu(v0.x + b0v), gelu(v0.y + b1v));
            hAU[base + 1] = pack_h(gelu(v1.x + b0v), gelu(v1.y + b1v));
        }
}

// ---------------- fused flow kernel: 32 tokens/CTA, 256 thr, 2 CTA/SM -------
__global__ __launch_bounds__(256, 2) void flow_kernel(
    const float* __restrict__ zin, const int* __restrict__ categ,
    const float* __restrict__ embed, const float* __restrict__ aW,
    const float* __restrict__ ab, const float* __restrict__ cW,
    const float* __restrict__ scf, const float* __restrict__ b0g,
    const float* __restrict__ b1g, const float* __restrict__ b2g,
    float* __restrict__ outz, float* __restrict__ ldj) {
    extern __shared__ float sm[];
    __shared__ int cat[32];
    __shared__ float wsum[8];
    const int tid = threadIdx.x, wid = tid >> 5, lane = tid & 31;
    const int m0 = wid * 4, tn = lane;
    const int t0 = blockIdx.x * MT;
    float* zef = sm + ZE;
    float* extf = sm + EXT;
    float* sb = sm + SB;
    float* ringF = sm + RING;
    U32* g3aU = (U32*)(sm + G3A);
    U32* hAU = (U32*)(sm + HA);
    const char* ringC = (const char*)(sm) + RING * 4;
    const U32 ringU = smem_u32(sm) + RING * 4;

    for (int i = tid; i < 2048; i += 256)
        zef[(i >> 6) * 68 + (i & 63)] = zin[(long long)t0 * 64 + i];
    if (tid < 32) cat[tid] = categ[t0 + tid];
    __syncthreads();
    for (int i = tid; i < 512; i += 256) {
        int m = i >> 4, e4 = i & 15;
        *(float4*)(extf + i * 4) = ((const float4*)embed)[(long long)cat[m] * 16 + e4];
    }
    __syncthreads();
    // pack ext -> G3A kt 2..5 (f16 A-frags), once
    for (int i = tid; i < 1024; i += 256) {
        int m = i >> 5, pe = i & 31;
        int kt = 2 + (pe >> 3), p = pe & 7;
        int ln = (m & 7) * 4 + (p & 3);
        int rr = ((m >> 3) & 1) + 2 * ((p >> 2) & 1);
        g3aU[((m >> 4) * 6 + kt) * 128 + ln * 4 + rr] =
            pack_h(extf[m * 64 + 2 * pe], extf[m * 64 + 2 * pe + 1]);
    }
    float ldj_acc = 0.f;

#pragma unroll 1
    for (int f = 0; f < 4; f++) {
        __syncthreads();
        for (int i = tid; i < 512; i += 256) sb[i] = b0g[f * 512 + i];
        for (int i = tid; i < 512; i += 256) sb[512 + i] = b1g[f * 512 + i];
        if (tid < 128) sb[1024 + tid] = b2g[f * 128 + tid];
        if (tid < 128) sb[1152 + tid] = ab[f * 128 + tid];
        stage_cp(ringU, aW + f * 8192, 2048, tid);  // 32KB fp32 into ring
        CPC(); CPW0();
        __syncthreads();

        // G1: actnorm (scalar fp32x2) — 4 tokens per warp
        {
            ULL acc[4][2];
#pragma unroll
            for (int i = 0; i < 4; i++) acc[i][0] = acc[i][1] = 0ull;
#pragma unroll 4
            for (int kk = 0; kk < 64; kk++) {
                ULL w0 = *(const ULL*)(ringF + kk * 128 + 2 * tn);
                ULL w1 = *(const ULL*)(ringF + kk * 128 + 64 + 2 * tn);
#pragma unroll
                for (int i = 0; i < 4; i++) {
                    ULL a = dup2(extf[(m0 + i) * 64 + kk]);
                    fma2(acc[i][0], a, w0);
                    fma2(acc[i][1], a, w1);
                }
            }
            int d0 = 2 * tn;
            float ab0 = sb[1152 + d0], ab1 = sb[1153 + d0];
            float as0 = sb[1216 + d0], as1 = sb[1217 + d0];
#pragma unroll
            for (int i = 0; i < 4; i++) {
                float2 bi = unpk(acc[i][0]);
                float2 sc = unpk(acc[i][1]);
                float s0 = tanhf(sc.x + as0), s1 = tanhf(sc.y + as1);
                float* zp = zef + (m0 + i) * 68 + d0;
                zp[0] = (zp[0] + bi.x + ab0) * expf(s0);
                zp[1] = (zp[1] + bi.y + ab1) * expf(s1);
                ldj_acc += s0 + s1;
            }
            __syncthreads();
        }
        // G2: 1x1 conv (scalar fp32x2)
        {
            stage_cp(ringU, cW + f * 4096, 1024, tid);
            CPC(); CPW0();
            __syncthreads();
            ULL acc[4];
#pragma unroll
            for (int i = 0; i < 4; i++) acc[i] = 0ull;
#pragma unroll 4
            for (int kk = 0; kk < 64; kk++) {
                ULL w = *(const ULL*)(ringF + kk * 64 + 2 * tn);
#pragma unroll
                for (int i = 0; i < 4; i++) fma2(acc[i], dup2(zef[(m0 + i) * 68 + kk]), w);
            }
            __syncthreads();
#pragma unroll
            for (int i = 0; i < 4; i++) {
                float2 v = unpk(acc[i]);
                zef[(m0 + i) * 68 + 2 * tn] = v.x;
                zef[(m0 + i) * 68 + 2 * tn + 1] = v.y;
            }
            __syncthreads();
        }
        // pack masked z -> G3A kt 0..1
        for (int i = tid; i < 512; i += 256) {
            int m = i >> 4, pe = i & 15;
            int kt = pe >> 3, p = pe & 7;
            int ln = (m & 7) * 4 + (p & 3);
            int rr = ((m >> 3) & 1) + 2 * ((p >> 2) & 1);
            g3aU[((m >> 4) * 6 + kt) * 128 + ln * 4 + rr] =
                pack_h(zef[m * 68 + 2 * pe], zef[m * 68 + 2 * pe + 1]);
        }

        U32 acc[16][2];
        // G3: K'=96 (6 iters)
#pragma unroll
        for (int i = 0; i < 16; i++) { acc[i][0] = 0u; acc[i][1] = 0u; }
        gemmW<6, 6>(acc, g_W0p + f * 6 * 4096, g3aU, ringU, ringC, lane, wid);
        __syncthreads();
        epiH(acc, sb, hAU, lane, wid);

        // G4: K=512 (32 iters)
#pragma unroll
        for (int i = 0; i < 16; i++) { acc[i][0] = 0u; acc[i][1] = 0u; }
        gemmW<32, 32>(acc, g_W1p + f * 32 * 4096, hAU, ringU, ringC, lane, wid);
        __syncthreads();
        epiH(acc, sb + 512, hAU, lane, wid);

        // G5: N=64, K=512 (8 iters)
#pragma unroll
        for (int i = 0; i < 2; i++) { acc[i][0] = 0u; acc[i][1] = 0u; }
        gemmG5(acc, g_W2p + f * 8 * 2048, hAU, ringU, ringC, lane, wid);
        {
            int cc = lane & 3, r = lane >> 2;
            int d = 32 + wid * 4 + cc;
            float sf = expf(scf[f * 64 + d]);
            float den = fmaxf(sf, 1.0f);
            float bs = sb[1088 + wid * 8 + 2 * cc];
            float bt = sb[1089 + wid * 8 + 2 * cc];
#pragma unroll
            for (int mtl = 0; mtl < 2; mtl++)
#pragma unroll
                for (int qh = 0; qh < 2; qh++) {
                    int m = mtl * 16 + r + 8 * qh;
                    float2 v = unpk_h(acc[mtl][qh]);
                    float sr = v.x + bs;
                    float tr = v.y + bt;
                    float s = tanhf(sr / den) * sf;
                    zef[m * 68 + d] = (zef[m * 68 + d] + tr) * expf(s);
                    ldj_acc += s;
                }
        }
    }  // flows

    __syncthreads();
    for (int i = tid; i < 2048; i += 256)
        outz[(long long)t0 * 64 + i] = zef[(i >> 6) * 68 + (i & 63)];
#pragma unroll
    for (int o = 16; o; o >>= 1) ldj_acc += __shfl_xor_sync(0xffffffffu, ldj_acc, o);
    if (lane == 0) wsum[wid] = ldj_acc;
    __syncthreads();
    if (tid == 0) {
        float s = 0.f;
#pragma unroll
        for (int i = 0; i < 8; i++) s += wsum[i];
        atomicAdd(&ldj[blockIdx.x >> 6], s);  // 64 blocks per batch
    }
}

// ---------------------------------------------------------------------------
extern "C" void kernel_launch(void* const* d_in, const int* in_sizes, int n_in,
                              void* d_out, int out_size) {
    const float* z = (const float*)d_in[0];
    const int* categ = (const int*)d_in[1];
    const float* embed = (const float*)d_in[2];
    const float* actnorm_W = (const float*)d_in[3];
    const float* actnorm_b = (const float*)d_in[4];
    const float* conv_W = (const float*)d_in[5];
    const float* scaling_factor = (const float*)d_in[6];
    const float* W0 = (const float*)d_in[7];
    const float* b0 = (const float*)d_in[8];
    const float* W1 = (const float*)d_in[9];
    const float* b1 = (const float*)d_in[10];
    const float* W2 = (const float*)d_in[11];
    const float* b2 = (const float*)d_in[12];

    float* outz = (float*)d_out;
    float* ldj = outz + (long long)TOKENS * 64;
    U32 *w0p, *w1p, *w2p;
    cudaGetSymbolAddress((void**)&w0p, g_W0p);
    cudaGetSymbolAddress((void**)&w1p, g_W1p);
    cudaGetSymbolAddress((void**)&w2p, g_W2p);

    cudaFuncSetAttribute(flow_kernel, cudaFuncAttributeMaxDynamicSharedMemorySize, SMEMB);

    packB<<<dim3(6, 4), 256>>>(W0, w0p, 512, 6, 1);
    packB<<<dim3(32, 4), 256>>>(W1, w1p, 512, 32, 0);
    packW2<<<dim3(8, 4), 256>>>(W2, w2p);
    logdet_kernel<<<4, 64>>>(conv_W);
    init_ldj_kernel<<<1, 64>>>(ldj);
    flow_kernel<<<NBLK, 256, SMEMB>>>(z, categ, embed, actnorm_W, actnorm_b, conv_W,
                                      scaling_factor, b0, b1, b2, outz, ldj);
}

// round 14
// speedup vs baseline: 1.2067x; 1.2067x over previous
#include <cuda_runtime.h>
#include <cuda_fp16.h>
#include <cstdint>

// B=64,S=2048,D=64,E=64,H=512,F=4,V=32000
#define TOKENS (64 * 2048)
#define MT 32
#define NBLK (TOKENS / MT)  // 4096
typedef unsigned long long ULL;
typedef unsigned int U32;

__device__ float g_logdet[4];
__device__ U32 g_W0p[4 * 6 * 4096];   // [f][kt<6][nt(64)*64] f16x2 frags (K'=96)
__device__ U32 g_W1p[4 * 32 * 4096];  // [f][kt<32][...]
__device__ U32 g_W2p[4 * 8 * 2048];   // [f][tile<8][s(4)][nt(8)][64], cols 64..127

// smem float offsets (total 27520 floats = 110080 B -> 2 CTAs/SM)
#define ZE 0       // 32 x 68 fp32 z
#define EXT 2176   // 32 x 64 fp32 ext (persistent)
#define SB 4224    // b0[512] b1[512] b2[128] ab[128]
#define G3A 5504   // 1536 u32: A frags [mtl(2)][kt(6)][128]
#define HA 7040    // 8192 u32: h A frags [mtl(2)][kt(32)][128]
#define RING 15232 // 3 x 4096 u32 (16KB slots)
#define SMEMF 27520
#define SMEMB (SMEMF * 4)

// ---------------- helpers ----------------
__device__ __forceinline__ ULL dup2(float a) {
    ULL r; U32 ai = __float_as_uint(a);
    asm("mov.b64 %0, {%1, %1};" : "=l"(r) : "r"(ai));
    return r;
}
__device__ __forceinline__ void fma2(ULL& d, ULL a, ULL b) {
    asm("fma.rn.f32x2 %0, %1, %2, %0;" : "+l"(d) : "l"(a), "l"(b));
}
__device__ __forceinline__ float2 unpk(ULL v) {
    U32 lo, hi;
    asm("mov.b64 {%0, %1}, %2;" : "=r"(lo), "=r"(hi) : "l"(v));
    float2 r; r.x = __uint_as_float(lo); r.y = __uint_as_float(hi);
    return r;
}
__device__ __forceinline__ float gelu(float x) {
    return 0.5f * x * (1.0f + erff(x * 0.70710678118654752440f));
}
__device__ __forceinline__ U32 pack_h(float lo, float hi) {
    U32 r;
    asm("cvt.rn.f16x2.f32 %0, %1, %2;" : "=r"(r) : "f"(hi), "f"(lo));
    return r;
}
__device__ __forceinline__ float2 unpk_h(U32 v) {
    __half2 h = *reinterpret_cast<__half2*>(&v);
    return __half22float2(h);
}
__device__ __forceinline__ U32 smem_u32(const void* p) {
    U32 a;
    asm("{ .reg .u64 t; cvta.to.shared.u64 t, %1; cvt.u32.u64 %0, t; }" : "=r"(a) : "l"(p));
    return a;
}
#define CPA16(d, s) asm volatile("cp.async.cg.shared.global [%0], [%1], 16;" ::"r"(d), "l"(s))
#define CPC() asm volatile("cp.async.commit_group;" ::: "memory")
#define CPW0() asm volatile("cp.async.wait_group 0;" ::: "memory")
#define CPW1() asm volatile("cp.async.wait_group 1;" ::: "memory")

// f16 x f16 -> f16 accumulate (2 c-regs of f16x2)
__device__ __forceinline__ void mma16h(U32* c, uint4 a, uint2 b) {
    asm volatile(
        "mma.sync.aligned.m16n8k16.row.col.f16.f16.f16.f16 "
        "{%0,%1},{%2,%3,%4,%5},{%6,%7},{%0,%1};"
        : "+r"(c[0]), "+r"(c[1])
        : "r"(a.x), "r"(a.y), "r"(a.z), "r"(a.w), "r"(b.x), "r"(b.y));
}
__device__ __forceinline__ void stage_cp(U32 dstU, const float* src, int n4, int tid) {
    for (int i = tid; i < n4; i += 256) CPA16(dstU + i * 16, src + i * 4);
}

// ---------------- prep kernel: LU logdet (blocks 0-3) + all weight packs ----
__global__ void prep_kernel(const float* __restrict__ cW, const float* __restrict__ W0,
                            const float* __restrict__ W1, const float* __restrict__ W2) {
    int b = blockIdx.x, tid = threadIdx.x;
    if (b < 4) {
        __shared__ float A[64][65];
        __shared__ int piv;
        int f = b;
        if (tid < 64)
            for (int j = 0; j < 64; j++) A[j][tid] = cW[f * 4096 + j * 64 + tid];
        __syncthreads();
        for (int j = 0; j < 64; j++) {
            if (tid == 0) {
                int p = j; float mv = fabsf(A[j][j]);
                for (int i = j + 1; i < 64; i++) {
                    float v = fabsf(A[i][j]);
                    if (v > mv) { mv = v; p = i; }
                }
                piv = p;
            }
            __syncthreads();
            if (tid < 64) {
                int p = piv;
                if (p != j) { float t = A[j][tid]; A[j][tid] = A[p][tid]; A[p][tid] = t; }
            }
            __syncthreads();
            if (tid < 64 && tid > j) {
                float fct = A[tid][j] / A[j][j];
                for (int k = j; k < 64; k++) A[tid][k] -= fct * A[j][k];
            }
            __syncthreads();
        }
        if (tid == 0) {
            float s = 0.f;
            for (int j = 0; j < 64; j++) s += logf(fabsf(A[j][j]));
            g_logdet[f] = s;
        }
    } else if (b < 28) {  // W0 pack (kMode): 24 blocks
        int idx = b - 4, f = idx / 6, kt = idx % 6;
        const float* s = W0 + (long long)f * 128 * 512;
        U32* d = g_W0p + (f * 6 + kt) * 4096;
        for (int i = tid; i < 4096; i += 256) {
            int nt = i >> 6, j = i & 63, lane = j >> 1, rr = j & 1;
            int k0 = kt * 16 + 2 * (lane & 3) + 8 * rr;
            int n = nt * 8 + (lane >> 2);
            if (k0 >= 32) k0 += 32;  // skip masked-z rows 32..63
            d[i] = pack_h(s[k0 * 512 + n], s[(k0 + 1) * 512 + n]);
        }
    } else if (b < 156) {  // W1 pack: 128 blocks
        int idx = b - 28, f = idx >> 5, kt = idx & 31;
        const float* s = W1 + (long long)f * 512 * 512;
        U32* d = g_W1p + (f * 32 + kt) * 4096;
        for (int i = tid; i < 4096; i += 256) {
            int nt = i >> 6, j = i & 63, lane = j >> 1, rr = j & 1;
            int k0 = kt * 16 + 2 * (lane & 3) + 8 * rr;
            int n = nt * 8 + (lane >> 2);
            d[i] = pack_h(s[k0 * 512 + n], s[(k0 + 1) * 512 + n]);
        }
    } else {  // W2 pack: 16 blocks (4 per flow)
        int idx = b - 156, f = idx >> 2, q = idx & 3;
        const float* s = W2 + (long long)f * 512 * 128;
        U32* d = g_W2p + f * 8 * 2048;
        for (int i = tid; i < 4096; i += 256) {
            int j = q * 4096 + i;
            int t = j >> 11, jj2 = j & 2047;
            int ss = jj2 >> 9, j2 = jj2 & 511;
            int nt = j2 >> 6, jj = j2 & 63, lane = jj >> 1, rr = jj & 1;
            int k0 = (t * 4 + ss) * 16 + 2 * (lane & 3) + 8 * rr;
            int n = 64 + nt * 8 + (lane >> 2);
            d[j] = pack_h(s[k0 * 128 + n], s[(k0 + 1) * 128 + n]);
        }
    }
}

// ------- gemm driver A: 16KB tiles, one k16 step, warp = 8 ntiles of N=512 ---
// NPRE tiles already staged (in flight) by caller into slots 0..NPRE-1.
template <int ITERS, int KTA, int NPRE>
__device__ __forceinline__ void gemmN8(U32 (*acc)[2], const U32* __restrict__ Bg,
                                       const U32* __restrict__ AU, U32 ringU,
                                       const U32* __restrict__ ringFU, int tid,
                                       int lane, int wid) {
    __syncthreads();
    for (int t = NPRE; t < 2 && t < ITERS; t++) {
        stage_cp(ringU + t * 16384, (const float*)(Bg + t * 4096), 1024, tid);
        CPC();
    }
    for (int it = 0; it < ITERS; it++) {
        if (it + 1 < ITERS) { CPW1(); } else { CPW0(); }
        __syncthreads();
        if (it + 2 < ITERS) {
            stage_cp(ringU + ((it + 2) % 3) * 16384,
                     (const float*)(Bg + (U32)(it + 2) * 4096), 1024, tid);
            CPC();
        }
        const U32* bp = ringFU + (it % 3) * 4096 + wid * 512 + lane * 2;
        uint4 a0 = *(const uint4*)(AU + (0 * KTA + it) * 128 + lane * 4);
        uint4 a1 = *(const uint4*)(AU + (1 * KTA + it) * 128 + lane * 4);
#pragma unroll
        for (int nt = 0; nt < 8; nt++) {
            uint2 bv = *(const uint2*)(bp + nt * 64);
            mma16h(acc[nt], a0, bv);
            mma16h(acc[8 + nt], a1, bv);
        }
    }
}
// ------- gemm driver B (G5): 8KB tiles, 4 k16 steps, warp = 1 ntile of N=64 --
template <int NPRE>
__device__ __forceinline__ void gemmG5(U32 (*acc)[2], const U32* __restrict__ Bg,
                                       const U32* __restrict__ AU, U32 ringU,
                                       const U32* __restrict__ ringFU, int tid,
                                       int lane, int wid) {
    __syncthreads();
    for (int t = NPRE; t < 2; t++) {
        stage_cp(ringU + t * 16384, (const float*)(Bg + t * 2048), 512, tid);
        CPC();
    }
    for (int it = 0; it < 8; it++) {
        if (it + 1 < 8) { CPW1(); } else { CPW0(); }
        __syncthreads();
        if (it + 2 < 8) {
            stage_cp(ringU + ((it + 2) % 3) * 16384,
                     (const float*)(Bg + (U32)(it + 2) * 2048), 512, tid);
            CPC();
        }
        const U32* slot = ringFU + (it % 3) * 4096 + wid * 64 + lane * 2;
#pragma unroll
        for (int s = 0; s < 4; s++) {
            int kt = it * 4 + s;
            uint2 bv = *(const uint2*)(slot + s * 512);
            uint4 a0 = *(const uint4*)(AU + (0 * 32 + kt) * 128 + lane * 4);
            uint4 a1 = *(const uint4*)(AU + (1 * 32 + kt) * 128 + lane * 4);
            mma16h(acc[0], a0, bv);
            mma16h(acc[1], a1, bv);
        }
    }
}

// epilogue: gelu(acc+bias) -> hA f16 A-frags (mtl 0..1, nt 0..7 per warp)
__device__ __forceinline__ void epiH(U32 (*acc)[2], const float* __restrict__ bias,
                                     U32* __restrict__ hAU, int lane, int wid) {
    int c2 = 2 * (lane & 3);
#pragma unroll
    for (int mtl = 0; mtl < 2; mtl++)
#pragma unroll
        for (int nt = 0; nt < 8; nt++) {
            int ntg = wid * 8 + nt;
            float2 v0 = unpk_h(acc[mtl * 8 + nt][0]);
            float2 v1 = unpk_h(acc[mtl * 8 + nt][1]);
            int n0 = ntg * 8 + c2;
            float b0v = bias[n0], b1v = bias[n0 + 1];
            U32 base = (U32)(mtl * 32 + (ntg >> 1)) * 128 + lane * 4 + 2 * (ntg & 1);
            hAU[base + 0] = pack_h(gelu(v0.x + b0v), gelu(v0.y + b1v));
            hAU[base + 1] = pack_h(gelu(v1.x + b0v), gelu(v1.y + b1v));
        }
}

// ---------------- fused flow kernel: 32 tokens/CTA, 256 thr, 2 CTA/SM -------
__global__ __launch_bounds__(256, 2) void flow_kernel(
    const float* __restrict__ zin, const int* __restrict__ categ,
    const float* __restrict__ embed, const float* __restrict__ aW,
    const float* __restrict__ ab, const float* __restrict__ cW,
    const float* __restrict__ scf, const float* __restrict__ b0g,
    const float* __restrict__ b1g, const float* __restrict__ b2g,
    float* __restrict__ outz, float* __restrict__ ldj) {
    extern __shared__ float sm[];
    __shared__ int cat[32];
    __shared__ float wsum[8];
    const int tid = threadIdx.x, wid = tid >> 5, lane = tid & 31;
    const int m0 = wid * 4, tn = lane;
    const int t0 = blockIdx.x * MT;
    float* zef = sm + ZE;
    float* extf = sm + EXT;
    float* sb = sm + SB;
    float* ringF = sm + RING;
    U32* g3aU = (U32*)(sm + G3A);
    U32* hAU = (U32*)(sm + HA);
    const U32* ringFU = (const U32*)(sm + RING);
    const U32 ringU = smem_u32(sm) + RING * 4;

    for (int i = tid; i < 2048; i += 256)
        zef[(i >> 6) * 68 + (i & 63)] = zin[(long long)t0 * 64 + i];
    if (tid < 32) cat[tid] = categ[t0 + tid];
    __syncthreads();
    for (int i = tid; i < 512; i += 256) {
        int m = i >> 4, e4 = i & 15;
        *(float4*)(extf + i * 4) = ((const float4*)embed)[(long long)cat[m] * 16 + e4];
    }
    __syncthreads();
    // pack ext -> G3A kt 2..5 (f16 A-frags), once
    for (int i = tid; i < 1024; i += 256) {
        int m = i >> 5, pe = i & 31;
        int kt = 2 + (pe >> 3), p = pe & 7;
        int ln = (m & 7) * 4 + (p & 3);
        int rr = ((m >> 3) & 1) + 2 * ((p >> 2) & 1);
        g3aU[((m >> 4) * 6 + kt) * 128 + ln * 4 + rr] =
            pack_h(extf[m * 64 + 2 * pe], extf[m * 64 + 2 * pe + 1]);
    }
    float ldj_acc = 0.f;

#pragma unroll 1
    for (int f = 0; f < 4; f++) {
        __syncthreads();
        for (int i = tid; i < 512; i += 256) sb[i] = b0g[f * 512 + i];
        for (int i = tid; i < 512; i += 256) sb[512 + i] = b1g[f * 512 + i];
        if (tid < 128) sb[1024 + tid] = b2g[f * 128 + tid];
        if (tid < 128) sb[1152 + tid] = ab[f * 128 + tid];
        stage_cp(ringU, aW + f * 8192, 2048, tid);  // 32KB fp32 into slots 0+1
        CPC(); CPW0();
        __syncthreads();

        // G1: actnorm (scalar fp32x2) — 4 tokens per warp
        {
            ULL acc[4][2];
#pragma unroll
            for (int i = 0; i < 4; i++) acc[i][0] = acc[i][1] = 0ull;
#pragma unroll 4
            for (int kk = 0; kk < 64; kk++) {
                ULL w0 = *(const ULL*)(ringF + kk * 128 + 2 * tn);
                ULL w1 = *(const ULL*)(ringF + kk * 128 + 64 + 2 * tn);
#pragma unroll
                for (int i = 0; i < 4; i++) {
                    ULL a = dup2(extf[(m0 + i) * 64 + kk]);
                    fma2(acc[i][0], a, w0);
                    fma2(acc[i][1], a, w1);
                }
            }
            int d0 = 2 * tn;
            float ab0 = sb[1152 + d0], ab1 = sb[1153 + d0];
            float as0 = sb[1216 + d0], as1 = sb[1217 + d0];
#pragma unroll
            for (int i = 0; i < 4; i++) {
                float2 bi = unpk(acc[i][0]);
                float2 sc = unpk(acc[i][1]);
                float s0 = tanhf(sc.x + as0), s1 = tanhf(sc.y + as1);
                float* zp = zef + (m0 + i) * 68 + d0;
                zp[0] = (zp[0] + bi.x + ab0) * expf(s0);
                zp[1] = (zp[1] + bi.y + ab1) * expf(s1);
                ldj_acc += s0 + s1;
            }
            __syncthreads();
        }
        // G2: 1x1 conv (scalar fp32x2)
        {
            stage_cp(ringU, cW + f * 4096, 1024, tid);  // cW -> slot 0
            CPC(); CPW0();
            __syncthreads();
            ULL acc[4];
#pragma unroll
            for (int i = 0; i < 4; i++) acc[i] = 0ull;
#pragma unroll 4
            for (int kk = 0; kk < 64; kk++) {
                ULL w = *(const ULL*)(ringF + kk * 64 + 2 * tn);
#pragma unroll
                for (int i = 0; i < 4; i++) fma2(acc[i], dup2(zef[(m0 + i) * 68 + kk]), w);
            }
            __syncthreads();
            // prefetch W0 tiles 0,1 into slots 0,1 (cW reads done; overlaps
            // zef writeback + z-pack below)
            stage_cp(ringU, (const float*)(g_W0p + f * 6 * 4096), 1024, tid);
            CPC();
            stage_cp(ringU + 16384, (const float*)(g_W0p + f * 6 * 4096 + 4096), 1024, tid);
            CPC();
#pragma unroll
            for (int i = 0; i < 4; i++) {
                float2 v = unpk(acc[i]);
                zef[(m0 + i) * 68 + 2 * tn] = v.x;
                zef[(m0 + i) * 68 + 2 * tn + 1] = v.y;
            }
            __syncthreads();
        }
        // pack masked z -> G3A kt 0..1
        for (int i = tid; i < 512; i += 256) {
            int m = i >> 4, pe = i & 15;
            int kt = pe >> 3, p = pe & 7;
            int ln = (m & 7) * 4 + (p & 3);
            int rr = ((m >> 3) & 1) + 2 * ((p >> 2) & 1);
            g3aU[((m >> 4) * 6 + kt) * 128 + ln * 4 + rr] =
                pack_h(zef[m * 68 + 2 * pe], zef[m * 68 + 2 * pe + 1]);
        }

        U32 acc[16][2];
        // G3: K'=96 (6 iters), tiles 0,1 prefetched
#pragma unroll
        for (int i = 0; i < 16; i++) { acc[i][0] = 0u; acc[i][1] = 0u; }
        gemmN8<6, 6, 2>(acc, g_W0p + f * 6 * 4096, g3aU, ringU, ringFU, tid, lane, wid);
        // prefetch W1 tiles 0,1 (slots 0,1 dead since G3 it3/it4 barriers)
        stage_cp(ringU, (const float*)(g_W1p + f * 32 * 4096), 1024, tid);
        CPC();
        stage_cp(ringU + 16384, (const float*)(g_W1p + f * 32 * 4096 + 4096), 1024, tid);
        CPC();
        __syncthreads();
        epiH(acc, sb, hAU, lane, wid);

        // G4: K=512 (32 iters), tiles 0,1 prefetched
#pragma unroll
        for (int i = 0; i < 16; i++) { acc[i][0] = 0u; acc[i][1] = 0u; }
        gemmN8<32, 32, 2>(acc, g_W1p + f * 32 * 4096, hAU, ringU, ringFU, tid, lane, wid);
        // prefetch W2 tile 0 only (slot1 live at G4 it31)
        stage_cp(ringU, (const float*)(g_W2p + f * 8 * 2048), 512, tid);
        CPC();
        __syncthreads();
        epiH(acc, sb + 512, hAU, lane, wid);

        // G5: N=64, K=512 (8 iters), tile 0 prefetched
#pragma unroll
        for (int i = 0; i < 2; i++) { acc[i][0] = 0u; acc[i][1] = 0u; }
        gemmG5<1>(acc, g_W2p + f * 8 * 2048, hAU, ringU, ringFU, tid, lane, wid);
        __syncthreads();
        {
            int cc = lane & 3, r = lane >> 2;
            int d = 32 + wid * 4 + cc;
            float sf = expf(scf[f * 64 + d]);
            float den = fmaxf(sf, 1.0f);
            float bs = sb[1088 + wid * 8 + 2 * cc];
            float bt = sb[1089 + wid * 8 + 2 * cc];
#pragma unroll
            for (int mtl = 0; mtl < 2; mtl++)
#pragma unroll
                for (int qh = 0; qh < 2; qh++) {
                    int m = mtl * 16 + r + 8 * qh;
                    float2 v = unpk_h(acc[mtl][qh]);
                    float sr = v.x + bs;
                    float tr = v.y + bt;
                    float s = tanhf(sr / den) * sf;
                    zef[m * 68 + d] = (zef[m * 68 + d] + tr) * expf(s);
                    ldj_acc += s;
                }
            __syncthreads();
        }
    }  // flows

    for (int i = tid; i < 2048; i += 256)
        outz[(long long)t0 * 64 + i] = zef[(i >> 6) * 68 + (i & 63)];
#pragma unroll
    for (int o = 16; o; o >>= 1) ldj_acc += __shfl_xor_sync(0xffffffffu, ldj_acc, o);
    if (lane == 0) wsum[wid] = ldj_acc;
    __syncthreads();
    if (tid == 0) {
        // fold conv slogdet term: 2048*sum(logdet) split over 64 blocks/batch
        float s = 32.0f * (g_logdet[0] + g_logdet[1] + g_logdet[2] + g_logdet[3]);
#pragma unroll
        for (int i = 0; i < 8; i++) s += wsum[i];
        atomicAdd(&ldj[blockIdx.x >> 6], s);  // 64 blocks per batch
    }
}

// ---------------------------------------------------------------------------
extern "C" void kernel_launch(void* const* d_in, const int* in_sizes, int n_in,
                              void* d_out, int out_size) {
    const float* z = (const float*)d_in[0];
    const int* categ = (const int*)d_in[1];
    const float* embed = (const float*)d_in[2];
    const float* actnorm_W = (const float*)d_in[3];
    const float* actnorm_b = (const float*)d_in[4];
    const float* conv_W = (const float*)d_in[5];
    const float* scaling_factor = (const float*)d_in[6];
    const float* W0 = (const float*)d_in[7];
    const float* b0 = (const float*)d_in[8];
    const float* W1 = (const float*)d_in[9];
    const float* b1 = (const float*)d_in[10];
    const float* W2 = (const float*)d_in[11];
    const float* b2 = (const float*)d_in[12];

    float* outz = (float*)d_out;
    float* ldj = outz + (long long)TOKENS * 64;

    cudaFuncSetAttribute(flow_kernel, cudaFuncAttributeMaxDynamicSharedMemorySize, SMEMB);

    prep_kernel<<<172, 256>>>(conv_W, W0, W1, W2);
    cudaMemsetAsync(ldj, 0, 64 * sizeof(float));
    flow_kernel<<<NBLK, 256, SMEMB>>>(z, categ, embed, actnorm_W, actnorm_b, conv_W,
                                      scaling_factor, b0, b1, b2, outz, ldj);
}

// round 15
// speedup vs baseline: 1.3750x; 1.1395x over previous
#include <cuda_runtime.h>
#include <cuda_fp16.h>
#include <cstdint>

#define TOKENS (64 * 2048)
#define MT 32
#define NBLK (TOKENS / MT)
typedef unsigned long long ULL;
typedef unsigned int U32;

__device__ float g_logdet[4];
__device__ U32 g_W0p[4 * 6 * 4096];
__device__ U32 g_W1p[4 * 32 * 4096];
__device__ U32 g_W2p[4 * 8 * 2048];
__device__ U32 g_aWp[4 * 4096];  // [f][kt(4)][ntg(16)][64]
__device__ U32 g_cWp[4 * 2048];  // [f][kt(4)][ntg(8)][64]

#define ZE 0
#define EXT 2176
#define SB 4224
#define G3A 5504   // [mtl(2)][kt(6)][128] u32 (kt0,1=masked z; kt2..5=ext)
#define HA 7040    // 8192 u32 h frags; first 1024 reused as zA [mtl(2)][kt(4)][128]
#define RING 15232
#define SMEMF 27520
#define SMEMB (SMEMF * 4)

__device__ __forceinline__ float gelu(float x) {
    return 0.5f * x * (1.0f + erff(x * 0.70710678118654752440f));
}
__device__ __forceinline__ U32 pack_h(float lo, float hi) {
    U32 r;
    asm("cvt.rn.f16x2.f32 %0, %1, %2;" : "=r"(r) : "f"(hi), "f"(lo));
    return r;
}
__device__ __forceinline__ float2 unpk_h(U32 v) {
    __half2 h = *reinterpret_cast<__half2*>(&v);
    return __half22float2(h);
}
__device__ __forceinline__ U32 smem_u32(const void* p) {
    U32 a;
    asm("{ .reg .u64 t; cvta.to.shared.u64 t, %1; cvt.u32.u64 %0, t; }" : "=r"(a) : "l"(p));
    return a;
}
#define CPA16(d, s) asm volatile("cp.async.cg.shared.global [%0], [%1], 16;" ::"r"(d), "l"(s))
#define CPC() asm volatile("cp.async.commit_group;" ::: "memory")
#define CPW0() asm volatile("cp.async.wait_group 0;" ::: "memory")
#define CPW1() asm volatile("cp.async.wait_group 1;" ::: "memory")

__device__ __forceinline__ void mma16h(U32* c, uint4 a, uint2 b) {
    asm volatile(
        "mma.sync.aligned.m16n8k16.row.col.f16.f16.f16.f16 "
        "{%0,%1},{%2,%3,%4,%5},{%6,%7},{%0,%1};"
        : "+r"(c[0]), "+r"(c[1])
        : "r"(a.x), "r"(a.y), "r"(a.z), "r"(a.w), "r"(b.x), "r"(b.y));
}
__device__ __forceinline__ void mma16f(float* c, uint4 a, uint2 b) {
    asm volatile(
        "mma.sync.aligned.m16n8k16.row.col.f32.f16.f16.f32 "
        "{%0,%1,%2,%3},{%4,%5,%6,%7},{%8,%9},{%0,%1,%2,%3};"
        : "+f"(c[0]), "+f"(c[1]), "+f"(c[2]), "+f"(c[3])
        : "r"(a.x), "r"(a.y), "r"(a.z), "r"(a.w), "r"(b.x), "r"(b.y));
}
__device__ __forceinline__ void stage_cp(U32 dstU, const float* src, int n4, int tid) {
    for (int i = tid; i < n4; i += 256) CPA16(dstU + i * 16, src + i * 4);
}

// ---------------- prep: LU + all weight packs ----------------
__global__ void prep_kernel(const float* __restrict__ cW, const float* __restrict__ W0,
                            const float* __restrict__ W1, const float* __restrict__ W2,
                            const float* __restrict__ aW) {
    int b = blockIdx.x, tid = threadIdx.x;
    if (b < 4) {
        __shared__ float A[64][65];
        __shared__ int piv;
        int f = b;
        if (tid < 64)
            for (int j = 0; j < 64; j++) A[j][tid] = cW[f * 4096 + j * 64 + tid];
        __syncthreads();
        for (int j = 0; j < 64; j++) {
            if (tid == 0) {
                int p = j; float mv = fabsf(A[j][j]);
                for (int i = j + 1; i < 64; i++) {
                    float v = fabsf(A[i][j]);
                    if (v > mv) { mv = v; p = i; }
                }
                piv = p;
            }
            __syncthreads();
            if (tid < 64) {
                int p = piv;
                if (p != j) { float t = A[j][tid]; A[j][tid] = A[p][tid]; A[p][tid] = t; }
            }
            __syncthreads();
            if (tid < 64 && tid > j) {
                float fct = A[tid][j] / A[j][j];
                for (int k = j; k < 64; k++) A[tid][k] -= fct * A[j][k];
            }
            __syncthreads();
        }
        if (tid == 0) {
            float s = 0.f;
            for (int j = 0; j < 64; j++) s += logf(fabsf(A[j][j]));
            g_logdet[f] = s;
        }
    } else if (b < 28) {  // W0
        int idx = b - 4, f = idx / 6, kt = idx % 6;
        const float* s = W0 + (long long)f * 128 * 512;
        U32* d = g_W0p + (f * 6 + kt) * 4096;
        for (int i = tid; i < 4096; i += 256) {
            int nt = i >> 6, j = i & 63, lane = j >> 1, rr = j & 1;
            int k0 = kt * 16 + 2 * (lane & 3) + 8 * rr;
            int n = nt * 8 + (lane >> 2);
            if (k0 >= 32) k0 += 32;
            d[i] = pack_h(s[k0 * 512 + n], s[(k0 + 1) * 512 + n]);
        }
    } else if (b < 156) {  // W1
        int idx = b - 28, f = idx >> 5, kt = idx & 31;
        const float* s = W1 + (long long)f * 512 * 512;
        U32* d = g_W1p + (f * 32 + kt) * 4096;
        for (int i = tid; i < 4096; i += 256) {
            int nt = i >> 6, j = i & 63, lane = j >> 1, rr = j & 1;
            int k0 = kt * 16 + 2 * (lane & 3) + 8 * rr;
            int n = nt * 8 + (lane >> 2);
            d[i] = pack_h(s[k0 * 512 + n], s[(k0 + 1) * 512 + n]);
        }
    } else if (b < 172) {  // W2
        int idx = b - 156, f = idx >> 2, q = idx & 3;
        const float* s = W2 + (long long)f * 512 * 128;
        U32* d = g_W2p + f * 8 * 2048;
        for (int i = tid; i < 4096; i += 256) {
            int j = q * 4096 + i;
            int t = j >> 11, jj2 = j & 2047;
            int ss = jj2 >> 9, j2 = jj2 & 511;
            int nt = j2 >> 6, jj = j2 & 63, lane = jj >> 1, rr = jj & 1;
            int k0 = (t * 4 + ss) * 16 + 2 * (lane & 3) + 8 * rr;
            int n = 64 + nt * 8 + (lane >> 2);
            d[j] = pack_h(s[k0 * 128 + n], s[(k0 + 1) * 128 + n]);
        }
    } else if (b < 176) {  // aW: [kt(4)][ntg(16)][64], N=128
        int f = b - 172;
        const float* s = aW + (long long)f * 64 * 128;
        U32* d = g_aWp + f * 4096;
        for (int i = tid; i < 4096; i += 256) {
            int kt = i >> 10, ntg = (i >> 6) & 15, j = i & 63, lane = j >> 1, rr = j & 1;
            int k0 = kt * 16 + 2 * (lane & 3) + 8 * rr;
            int n = ntg * 8 + (lane >> 2);
            d[i] = pack_h(s[k0 * 128 + n], s[(k0 + 1) * 128 + n]);
        }
    } else {  // cW: [kt(4)][ntg(8)][64], N=64
        int f = b - 176;
        const float* s = cW + (long long)f * 64 * 64;
        U32* d = g_cWp + f * 2048;
        for (int i = tid; i < 2048; i += 256) {
            int kt = i >> 9, ntg = (i >> 6) & 7, j = i & 63, lane = j >> 1, rr = j & 1;
            int k0 = kt * 16 + 2 * (lane & 3) + 8 * rr;
            int n = ntg * 8 + (lane >> 2);
            d[i] = pack_h(s[k0 * 64 + n], s[(k0 + 1) * 64 + n]);
        }
    }
}

// ------- gemm driver A: 16KB tiles, warp = 8 ntiles of N=512 -----------------
template <int ITERS, int KTA, int NPRE>
__device__ __forceinline__ void gemmN8(U32 (*acc)[2], const U32* __restrict__ Bg,
                                       const U32* __restrict__ AU, U32 ringU,
                                       const U32* __restrict__ ringFU, int tid,
                                       int lane, int wid) {
    __syncthreads();
    for (int t = NPRE; t < 2 && t < ITERS; t++) {
        stage_cp(ringU + t * 16384, (const float*)(Bg + t * 4096), 1024, tid);
        CPC();
    }
    for (int it = 0; it < ITERS; it++) {
        if (it + 1 < ITERS) { CPW1(); } else { CPW0(); }
        __syncthreads();
        if (it + 2 < ITERS) {
            stage_cp(ringU + ((it + 2) % 3) * 16384,
                     (const float*)(Bg + (U32)(it + 2) * 4096), 1024, tid);
            CPC();
        }
        const U32* bp = ringFU + (it % 3) * 4096 + wid * 512 + lane * 2;
        uint4 a0 = *(const uint4*)(AU + (0 * KTA + it) * 128 + lane * 4);
        uint4 a1 = *(const uint4*)(AU + (1 * KTA + it) * 128 + lane * 4);
#pragma unroll
        for (int nt = 0; nt < 8; nt++) {
            uint2 bv = *(const uint2*)(bp + nt * 64);
            mma16h(acc[nt], a0, bv);
            mma16h(acc[8 + nt], a1, bv);
        }
    }
}
// ------- G5 gemm: 8KB tiles, warp = 1 ntile of N=64 --------------------------
template <int NPRE>
__device__ __forceinline__ void gemmG5(U32 (*acc)[2], const U32* __restrict__ Bg,
                                       const U32* __restrict__ AU, U32 ringU,
                                       const U32* __restrict__ ringFU, int tid,
                                       int lane, int wid) {
    __syncthreads();
    for (int t = NPRE; t < 2; t++) {
        stage_cp(ringU + t * 16384, (const float*)(Bg + t * 2048), 512, tid);
        CPC();
    }
    for (int it = 0; it < 8; it++) {
        if (it + 1 < 8) { CPW1(); } else { CPW0(); }
        __syncthreads();
        if (it + 2 < 8) {
            stage_cp(ringU + ((it + 2) % 3) * 16384,
                     (const float*)(Bg + (U32)(it + 2) * 2048), 512, tid);
            CPC();
        }
        const U32* slot = ringFU + (it % 3) * 4096 + wid * 64 + lane * 2;
#pragma unroll
        for (int s = 0; s < 4; s++) {
            int kt = it * 4 + s;
            uint2 bv = *(const uint2*)(slot + s * 512);
            uint4 a0 = *(const uint4*)(AU + (0 * 32 + kt) * 128 + lane * 4);
            uint4 a1 = *(const uint4*)(AU + (1 * 32 + kt) * 128 + lane * 4);
            mma16h(acc[0], a0, bv);
            mma16h(acc[1], a1, bv);
        }
    }
}

__device__ __forceinline__ void epiH(U32 (*acc)[2], const float* __restrict__ bias,
                                     U32* __restrict__ hAU, int lane, int wid) {
    int c2 = 2 * (lane & 3);
#pragma unroll
    for (int mtl = 0; mtl < 2; mtl++)
#pragma unroll
        for (int nt = 0; nt < 8; nt++) {
            int ntg = wid * 8 + nt;
            float2 v0 = unpk_h(acc[mtl * 8 + nt][0]);
            float2 v1 = unpk_h(acc[mtl * 8 + nt][1]);
            int n0 = ntg * 8 + c2;
            float b0v = bias[n0], b1v = bias[n0 + 1];
            U32 base = (U32)(mtl * 32 + (ntg >> 1)) * 128 + lane * 4 + 2 * (ntg & 1);
            hAU[base + 0] = pack_h(gelu(v0.x + b0v), gelu(v0.y + b1v));
            hAU[base + 1] = pack_h(gelu(v1.x + b0v), gelu(v1.y + b1v));
        }
}

// ---------------- fused flow kernel ----------------
__global__ __launch_bounds__(256, 2) void flow_kernel(
    const float* __restrict__ zin, const int* __restrict__ categ,
    const float* __restrict__ embed, const float* __restrict__ scf,
    const float* __restrict__ abg, const float* __restrict__ b0g,
    const float* __restrict__ b1g, const float* __restrict__ b2g,
    float* __restrict__ outz, float* __restrict__ ldj) {
    extern __shared__ float sm[];
    __shared__ int cat[32];
    __shared__ float wsum[8];
    const int tid = threadIdx.x, wid = tid >> 5, lane = tid & 31;
    const int t0 = blockIdx.x * MT;
    float* zef = sm + ZE;
    float* extf = sm + EXT;
    float* sb = sm + SB;
    U32* g3aU = (U32*)(sm + G3A);
    U32* hAU = (U32*)(sm + HA);
    U32* zAU = hAU;  // transient overlay
    const U32* ringFU = (const U32*)(sm + RING);
    const U32 ringU = smem_u32(sm) + RING * 4;
    const int r = lane >> 2, c2 = 2 * (lane & 3);

    for (int i = tid; i < 2048; i += 256)
        zef[(i >> 6) * 68 + (i & 63)] = zin[(long long)t0 * 64 + i];
    if (tid < 32) cat[tid] = categ[t0 + tid];
    __syncthreads();
    for (int i = tid; i < 512; i += 256) {
        int m = i >> 4, e4 = i & 15;
        *(float4*)(extf + i * 4) = ((const float4*)embed)[(long long)cat[m] * 16 + e4];
    }
    __syncthreads();
    for (int i = tid; i < 1024; i += 256) {  // ext -> G3A kt2..5
        int m = i >> 5, pe = i & 31;
        int kt = 2 + (pe >> 3), p = pe & 7;
        int ln = (m & 7) * 4 + (p & 3);
        int rr = ((m >> 3) & 1) + 2 * ((p >> 2) & 1);
        g3aU[((m >> 4) * 6 + kt) * 128 + ln * 4 + rr] =
            pack_h(extf[m * 64 + 2 * pe], extf[m * 64 + 2 * pe + 1]);
    }
    float ldj_acc = 0.f;

#pragma unroll 1
    for (int f = 0; f < 4; f++) {
        __syncthreads();
        for (int i = tid; i < 512; i += 256) sb[i] = b0g[f * 512 + i];
        for (int i = tid; i < 512; i += 256) sb[512 + i] = b1g[f * 512 + i];
        if (tid < 128) sb[1024 + tid] = b2g[f * 128 + tid];
        if (tid < 128) sb[1152 + tid] = abg[f * 128 + tid];
        stage_cp(ringU, (const float*)(g_aWp + f * 4096), 1024, tid);       // slot0
        CPC();
        stage_cp(ringU + 32768, (const float*)(g_cWp + f * 2048), 512, tid);  // slot2
        CPC(); CPW0();
        __syncthreads();

        // G1: actnorm via mma (f32 acc). warp w -> ntiles {w (bias), w+8 (scales)}
        {
            float ga[4][4];
#pragma unroll
            for (int i = 0; i < 4; i++)
#pragma unroll
                for (int q = 0; q < 4; q++) ga[i][q] = 0.f;
#pragma unroll
            for (int kt = 0; kt < 4; kt++) {
                const U32* bp = ringFU + kt * 1024 + lane * 2;
                uint4 a0 = *(const uint4*)(g3aU + (0 * 6 + 2 + kt) * 128 + lane * 4);
                uint4 a1 = *(const uint4*)(g3aU + (1 * 6 + 2 + kt) * 128 + lane * 4);
                uint2 bv0 = *(const uint2*)(bp + wid * 64);
                uint2 bv1 = *(const uint2*)(bp + (wid + 8) * 64);
                mma16f(ga[0], a0, bv0); mma16f(ga[1], a0, bv1);
                mma16f(ga[2], a1, bv0); mma16f(ga[3], a1, bv1);
            }
            int d = 8 * wid + c2;
            float ab0 = sb[1152 + d], ab1 = sb[1153 + d];
            float as0 = sb[1216 + d], as1 = sb[1217 + d];
            int kp = 4 * wid + (c2 >> 1), p = kp & 7, ktz = kp >> 3;
#pragma unroll
            for (int mtl = 0; mtl < 2; mtl++)
#pragma unroll
                for (int qh = 0; qh < 2; qh++) {
                    int m = mtl * 16 + r + 8 * qh;
                    float s0 = tanhf(ga[mtl * 2 + 1][2 * qh] + as0);
                    float s1 = tanhf(ga[mtl * 2 + 1][2 * qh + 1] + as1);
                    float2 zo = *(const float2*)(zef + m * 68 + d);
                    float z0 = (zo.x + ga[mtl * 2][2 * qh] + ab0) * expf(s0);
                    float z1 = (zo.y + ga[mtl * 2][2 * qh + 1] + ab1) * expf(s1);
                    ldj_acc += s0 + s1;
                    int ln = (m & 7) * 4 + (p & 3);
                    int rr = ((m >> 3) & 1) + 2 * ((p >> 2) & 1);
                    zAU[(mtl * 4 + ktz) * 128 + ln * 4 + rr] = pack_h(z0, z1);
                }
        }
        __syncthreads();  // zA ready; slot0 free
        // prefetch W0 tiles 0,1 into slots 0,1
        stage_cp(ringU, (const float*)(g_W0p + f * 6 * 4096), 1024, tid);
        CPC();
        stage_cp(ringU + 16384, (const float*)(g_W0p + f * 6 * 4096 + 4096), 1024, tid);
        CPC();

        // G2: conv via mma (f32 acc). warp w -> ntile w (cols 8w..8w+7)
        {
            float gc[2][4];
#pragma unroll
            for (int i = 0; i < 2; i++)
#pragma unroll
                for (int q = 0; q < 4; q++) gc[i][q] = 0.f;
#pragma unroll
            for (int kt = 0; kt < 4; kt++) {
                const U32* bp = ringFU + 2 * 4096 + kt * 512 + wid * 64 + lane * 2;
                uint4 a0 = *(const uint4*)(zAU + (0 * 4 + kt) * 128 + lane * 4);
                uint4 a1 = *(const uint4*)(zAU + (1 * 4 + kt) * 128 + lane * 4);
                uint2 bv = *(const uint2*)bp;
                mma16f(gc[0], a0, bv);
                mma16f(gc[1], a1, bv);
            }
            __syncthreads();  // zA reads done before G3A kt0,1 overwrite? (G3A separate; zef writes safe)
            int n = 8 * wid + c2;
            int kp = n >> 1, p = kp & 7, ktz = kp >> 3;
#pragma unroll
            for (int mtl = 0; mtl < 2; mtl++)
#pragma unroll
                for (int qh = 0; qh < 2; qh++) {
                    int m = mtl * 16 + r + 8 * qh;
                    float z0 = gc[mtl][2 * qh], z1 = gc[mtl][2 * qh + 1];
                    *(float2*)(zef + m * 68 + n) = make_float2(z0, z1);
                    if (wid < 4) {
                        int ln = (m & 7) * 4 + (p & 3);
                        int rr = ((m >> 3) & 1) + 2 * ((p >> 2) & 1);
                        g3aU[(mtl * 6 + ktz) * 128 + ln * 4 + rr] = pack_h(z0, z1);
                    }
                }
        }

        U32 acc[16][2];
#pragma unroll
        for (int i = 0; i < 16; i++) { acc[i][0] = 0u; acc[i][1] = 0u; }
        gemmN8<6, 6, 2>(acc, g_W0p + f * 6 * 4096, g3aU, ringU, ringFU, tid, lane, wid);
        stage_cp(ringU, (const float*)(g_W1p + f * 32 * 4096), 1024, tid);
        CPC();
        stage_cp(ringU + 16384, (const float*)(g_W1p + f * 32 * 4096 + 4096), 1024, tid);
        CPC();
        __syncthreads();
        epiH(acc, sb, hAU, lane, wid);

#pragma unroll
        for (int i = 0; i < 16; i++) { acc[i][0] = 0u; acc[i][1] = 0u; }
        gemmN8<32, 32, 2>(acc, g_W1p + f * 32 * 4096, hAU, ringU, ringFU, tid, lane, wid);
        stage_cp(ringU, (const float*)(g_W2p + f * 8 * 2048), 512, tid);
        CPC();
        __syncthreads();
        epiH(acc, sb + 512, hAU, lane, wid);

#pragma unroll
        for (int i = 0; i < 2; i++) { acc[i][0] = 0u; acc[i][1] = 0u; }
        gemmG5<1>(acc, g_W2p + f * 8 * 2048, hAU, ringU, ringFU, tid, lane, wid);
        __syncthreads();
        {
            int cc = lane & 3;
            int d = 32 + wid * 4 + cc;
            float sf = expf(scf[f * 64 + d]);
            float den = fmaxf(sf, 1.0f);
            float bs = sb[1088 + wid * 8 + 2 * cc];
            float bt = sb[1089 + wid * 8 + 2 * cc];
#pragma unroll
            for (int mtl = 0; mtl < 2; mtl++)
#pragma unroll
                for (int qh = 0; qh < 2; qh++) {
                    int m = mtl * 16 + r + 8 * qh;
                    float2 v = unpk_h(acc[mtl][qh]);
                    float s = tanhf((v.x + bs) / den) * sf;
                    zef[m * 68 + d] = (zef[m * 68 + d] + v.y + bt) * expf(s);
                    ldj_acc += s;
                }
            __syncthreads();
        }
    }  // flows

    for (int i = tid; i < 2048; i += 256)
        outz[(long long)t0 * 64 + i] = zef[(i >> 6) * 68 + (i & 63)];
#pragma unroll
    for (int o = 16; o; o >>= 1) ldj_acc += __shfl_xor_sync(0xffffffffu, ldj_acc, o);
    if (lane == 0) wsum[wid] = ldj_acc;
    __syncthreads();
    if (tid == 0) {
        float s = 32.0f * (g_logdet[0] + g_logdet[1] + g_logdet[2] + g_logdet[3]);
#pragma unroll
        for (int i = 0; i < 8; i++) s += wsum[i];
        atomicAdd(&ldj[blockIdx.x >> 6], s);
    }
}

// ---------------------------------------------------------------------------
extern "C" void kernel_launch(void* const* d_in, const int* in_sizes, int n_in,
                              void* d_out, int out_size) {
    const float* z = (const float*)d_in[0];
    const int* categ = (const int*)d_in[1];
    const float* embed = (const float*)d_in[2];
    const float* actnorm_W = (const float*)d_in[3];
    const float* actnorm_b = (const float*)d_in[4];
    const float* conv_W = (const float*)d_in[5];
    const float* scaling_factor = (const float*)d_in[6];
    const float* W0 = (const float*)d_in[7];
    const float* b0 = (const float*)d_in[8];
    const float* W1 = (const float*)d_in[9];
    const float* b1 = (const float*)d_in[10];
    const float* W2 = (const float*)d_in[11];
    const float* b2 = (const float*)d_in[12];

    float* outz = (float*)d_out;
    float* ldj = outz + (long long)TOKENS * 64;

    cudaFuncSetAttribute(flow_kernel, cudaFuncAttributeMaxDynamicSharedMemorySize, SMEMB);

    prep_kernel<<<180, 256>>>(conv_W, W0, W1, W2, actnorm_W);
    cudaMemsetAsync(ldj, 0, 64 * sizeof(float));
    flow_kernel<<<NBLK, 256, SMEMB>>>(z, categ, embed, scaling_factor, actnorm_b,
                                      b0, b1, b2, outz, ldj);
}